// round 1
// baseline (speedup 1.0000x reference)
#include <cuda_runtime.h>
#include <math.h>

// Problem constants (fixed dataset)
#define NREV 4096
#define LTOK 128
#define DW   200
#define AASP 32
#define NNEG 5
#define BUSR 1024

// ---------------- scratch (device globals; no allocation allowed) ------------
__device__ __align__(16) float g_q[NREV * DW];      // rev_pos @ M_w
__device__ __align__(16) float g_rs[NREV * DW];     // r_s
__device__ float g_hinge[NREV];                     // per-review sum of hinges
__device__ __align__(16) float g_uemb[BUSR * DW];
__device__ __align__(16) float g_iemb[BUSR * DW];
__device__ float g_sq[BUSR];
__device__ float g_U[1];

// ---------------- block reduce (blockDim == 256, deterministic) --------------
__device__ __forceinline__ float blk_reduce(float v, float* scratch) {
    __syncthreads();                       // protect scratch reuse across calls
    #pragma unroll
    for (int o = 16; o; o >>= 1) v += __shfl_down_sync(0xffffffffu, v, o);
    int w = threadIdx.x >> 5;
    if ((threadIdx.x & 31) == 0) scratch[w] = v;
    __syncthreads();
    float r = (threadIdx.x < 8) ? scratch[threadIdx.x] : 0.f;
    if (w == 0) {
        #pragma unroll
        for (int o = 4; o; o >>= 1) r += __shfl_down_sync(0xffffffffu, r, o);
        if (threadIdx.x == 0) scratch[0] = r;
    }
    __syncthreads();
    return scratch[0];
}

// ---------------- K1: q = rev_pos @ M_w  ([4096,200]@[200,200]) --------------
// Block handles 16 reviews; M_w staged in SMEM; 4x4 register blocking.
__global__ __launch_bounds__(256, 1)
void qk(const float* __restrict__ rp, const float* __restrict__ Mw) {
    extern __shared__ float sm[];
    float* Ms  = sm;            // 40000 floats
    float* rps = sm + DW * DW;  // 16*200 floats
    int tid = threadIdx.x;
    for (int i = tid; i < DW * DW; i += 256) Ms[i] = Mw[i];
    int n0 = blockIdx.x * 16;
    for (int i = tid; i < 16 * DW; i += 256) rps[i] = rp[n0 * DW + i];
    __syncthreads();

    int g  = tid >> 6;   // 4 groups of 64 threads; group handles 4 reviews
    int dl = tid & 63;   // each thread covers d = dl, dl+64, dl+128, dl+192
    float acc[4][4];
    #pragma unroll
    for (int j = 0; j < 4; j++)
        #pragma unroll
        for (int k = 0; k < 4; k++) acc[j][k] = 0.f;

    for (int d2 = 0; d2 < DW; d2++) {
        float r0 = rps[(g * 4 + 0) * DW + d2];
        float r1 = rps[(g * 4 + 1) * DW + d2];
        float r2 = rps[(g * 4 + 2) * DW + d2];
        float r3 = rps[(g * 4 + 3) * DW + d2];
        #pragma unroll
        for (int k = 0; k < 4; k++) {
            int d = dl + k * 64;
            float m = (d < DW) ? Ms[d2 * DW + d] : 0.f;
            acc[0][k] += r0 * m;
            acc[1][k] += r1 * m;
            acc[2][k] += r2 * m;
            acc[3][k] += r3 * m;
        }
    }
    #pragma unroll
    for (int j = 0; j < 4; j++)
        #pragma unroll
        for (int k = 0; k < 4; k++) {
            int d = dl + k * 64;
            if (d < DW) g_q[(n0 + g * 4 + j) * DW + d] = acc[j][k];
        }
}

// ---------------- K2: per-review fused ABAE kernel ---------------------------
// One CTA per review. e_w tile (128x200 f32 = 102.4KB) staged once in SMEM.
__global__ __launch_bounds__(256, 2)
void mainkern(const int* __restrict__ hist, const float* __restrict__ wemb,
              const float* __restrict__ rneg, const float* __restrict__ Ww,
              const float* __restrict__ Wb, const float* __restrict__ Tw) {
    extern __shared__ float sm[];
    float* e   = sm;            // 25600  (flat [l*200+d])
    float* qs  = e + 25600;     // 200
    float* ax  = qs + 200;      // 128
    float* zs  = ax + 128;      // 200
    float* p   = zs + 200;      // 32
    float* red = p + 32;        // 32
    int*   tok = (int*)(red + 32); // 128

    int n    = blockIdx.x;
    int tid  = threadIdx.x;
    int w    = tid >> 5;
    int lane = tid & 31;

    if (tid < LTOK) tok[tid] = hist[n * LTOK + tid];
    if (tid < DW)   qs[tid]  = g_q[n * DW + tid];
    __syncthreads();

    // ---- gather e_w (vectorized: 50 float4 per 200-float row) ----
    const float4* we4 = (const float4*)wemb;
    float4* e4 = (float4*)e;
    for (int i = tid; i < LTOK * 50; i += 256) {
        int l = i / 50, j = i - l * 50;
        e4[l * 50 + j] = we4[tok[l] * 50 + j];
    }
    __syncthreads();

    // ---- dx[l] = e_w[l] . q ;  warp w handles 16 tokens ----
    for (int t = 0; t < 16; t++) {
        int l = w * 16 + t;
        float acc = 0.f;
        for (int d = lane; d < DW; d += 32) acc += e[l * DW + d] * qs[d];
        #pragma unroll
        for (int o = 16; o; o >>= 1) acc += __shfl_down_sync(0xffffffffu, acc, o);
        if (lane == 0) ax[l] = acc;
    }
    __syncthreads();

    // ---- softmax over 128 tokens (warp 0) ----
    if (w == 0) {
        float v0 = ax[lane], v1 = ax[lane + 32], v2 = ax[lane + 64], v3 = ax[lane + 96];
        float m = fmaxf(fmaxf(v0, v1), fmaxf(v2, v3));
        #pragma unroll
        for (int o = 16; o; o >>= 1) m = fmaxf(m, __shfl_xor_sync(0xffffffffu, m, o));
        v0 = expf(v0 - m); v1 = expf(v1 - m); v2 = expf(v2 - m); v3 = expf(v3 - m);
        float s = v0 + v1 + v2 + v3;
        #pragma unroll
        for (int o = 16; o; o >>= 1) s += __shfl_xor_sync(0xffffffffu, s, o);
        float inv = 1.f / s;
        ax[lane] = v0 * inv; ax[lane + 32] = v1 * inv;
        ax[lane + 64] = v2 * inv; ax[lane + 96] = v3 * inv;
    }
    __syncthreads();

    // ---- z_s via the reference's reshape trick: z[d] = sum_l e_flat[d*128+l]*ax[l]
    for (int i = 0; i < 25; i++) {
        int d = w * 25 + i;
        float acc = e[d * LTOK + lane]      * ax[lane]
                  + e[d * LTOK + lane + 32] * ax[lane + 32]
                  + e[d * LTOK + lane + 64] * ax[lane + 64]
                  + e[d * LTOK + lane + 96] * ax[lane + 96];
        #pragma unroll
        for (int o = 16; o; o >>= 1) acc += __shfl_down_sync(0xffffffffu, acc, o);
        if (lane == 0) zs[d] = acc;
    }
    __syncthreads();

    // ---- logits = z_s @ W_w^T + W_b ;  warp w handles a in {w, w+8, w+16, w+24}
    #pragma unroll
    for (int j = 0; j < 4; j++) {
        int a = w + 8 * j;
        float acc = 0.f;
        for (int d = lane; d < DW; d += 32) acc += zs[d] * Ww[a * DW + d];
        #pragma unroll
        for (int o = 16; o; o >>= 1) acc += __shfl_down_sync(0xffffffffu, acc, o);
        if (lane == 0) p[a] = acc + Wb[a];
    }
    __syncthreads();

    // ---- softmax over A=32 (warp 0) ----
    if (w == 0) {
        float v = p[lane];
        float m = v;
        #pragma unroll
        for (int o = 16; o; o >>= 1) m = fmaxf(m, __shfl_xor_sync(0xffffffffu, m, o));
        float ex = expf(v - m);
        float s = ex;
        #pragma unroll
        for (int o = 16; o; o >>= 1) s += __shfl_xor_sync(0xffffffffu, s, o);
        p[lane] = ex / s;
    }
    __syncthreads();

    // ---- r_s = p @ T_w^T ; write to global; keep in regs ----
    float rsv = 0.f, zsv = 0.f;
    if (tid < DW) {
        const float4* T4 = (const float4*)Tw;   // T_w is [200,32] row-major
        float acc = 0.f;
        #pragma unroll
        for (int j = 0; j < 8; j++) {
            float4 t = T4[tid * 8 + j];
            acc += t.x * p[j * 4 + 0] + t.y * p[j * 4 + 1]
                 + t.z * p[j * 4 + 2] + t.w * p[j * 4 + 3];
        }
        g_rs[n * DW + tid] = acc;
        rsv = acc;
        zsv = zs[tid];
    }

    // ---- cosine c1, hinges vs 5 negatives ----
    float s_zz = blk_reduce(zsv * zsv, red);
    float s_rr = blk_reduce(rsv * rsv, red);
    float s_zr = blk_reduce(zsv * rsv, red);
    float nz = fmaxf(sqrtf(s_zz), 1e-12f);
    float nr = fmaxf(sqrtf(s_rr), 1e-12f);
    float c1 = s_zr / (nz * nr);

    float h = 0.f;
    for (int k = 0; k < NNEG; k++) {
        float x = (tid < DW) ? rneg[(n * NNEG + k) * DW + tid] : 0.f;
        float s_nn = blk_reduce(x * x, red);
        float s_dn = blk_reduce(x * rsv, red);
        float c2 = s_dn / (fmaxf(sqrtf(s_nn), 1e-12f) * nr);
        h += fmaxf(0.f, c2 - c1);
    }
    if (tid == 0) g_hinge[n] = h;
}

// ---------------- K3: U_loss (tiny, one block) --------------------------------
__global__ __launch_bounds__(256, 1)
void ukern(const float* __restrict__ Tw) {
    __shared__ float Ts[DW * AASP];
    __shared__ float nrm[AASP];
    __shared__ float red[8];
    int tid = threadIdx.x;
    for (int i = tid; i < DW * AASP; i += 256) Ts[i] = Tw[i];
    __syncthreads();
    if (tid < AASP) {
        float s = 0.f;
        for (int d = 0; d < DW; d++) { float v = Ts[d * AASP + tid]; s += v * v; }
        nrm[tid] = fmaxf(sqrtf(s), 1e-12f);
    }
    __syncthreads();
    float part = 0.f;
    for (int pr = tid; pr < AASP * AASP; pr += 256) {
        int a = pr >> 5, b = pr & 31;
        float s = 0.f;
        for (int d = 0; d < DW; d++) s += Ts[d * AASP + a] * Ts[d * AASP + b];
        float g = s / (nrm[a] * nrm[b]);
        float diff = g - ((a == b) ? 1.f : 0.f);
        part += diff * diff;
    }
    float tot = blk_reduce(part, red);
    if (tid == 0) g_U[0] = tot / (float)(AASP * AASP);
}

// ---------------- K4: segment means via binary search on sorted seg ids -------
__global__ __launch_bounds__(256, 8)
void segkern(const int* __restrict__ uhi, const int* __restrict__ usi,
             const int* __restrict__ ihi, const int* __restrict__ isi, int F) {
    int b = blockIdx.x;
    const int* idx = blockIdx.y ? ihi : uhi;
    const int* seg = blockIdx.y ? isi : usi;
    float* out = blockIdx.y ? g_iemb : g_uemb;
    __shared__ int bnd[2];
    if (threadIdx.x == 0) {
        int lo = 0, hi = F;
        while (lo < hi) { int m = (lo + hi) >> 1; if (seg[m] < b) lo = m + 1; else hi = m; }
        bnd[0] = lo;
        int lo2 = lo, hi2 = F;
        while (lo2 < hi2) { int m = (lo2 + hi2) >> 1; if (seg[m] < b + 1) lo2 = m + 1; else hi2 = m; }
        bnd[1] = lo2;
    }
    __syncthreads();
    int lo = bnd[0], cnt = bnd[1] - bnd[0];
    float inv = 1.f / (float)cnt;
    for (int d = threadIdx.x; d < DW; d += blockDim.x) {
        float s = 0.f;
        for (int j = 0; j < cnt; j++) s += g_rs[idx[lo + j] * DW + d];
        out[b * DW + d] = s * inv;
    }
}

// ---------------- K5: prediction squared errors --------------------------------
__global__ __launch_bounds__(256, 4)
void predkern(const float* __restrict__ label, int B) {
    int b = blockIdx.x * blockDim.x + threadIdx.x;
    if (b >= B) return;
    const float4* u4 = (const float4*)(g_uemb + b * DW);
    const float4* i4 = (const float4*)(g_iemb + b * DW);
    float dot = 0.f;
    #pragma unroll 5
    for (int j = 0; j < DW / 4; j++) {
        float4 u = u4[j], v = i4[j];
        dot += u.x * v.x + u.y * v.y + u.z * v.z + u.w * v.w;
    }
    float e = dot + 3.5f - label[b];
    g_sq[b] = e * e;
}

// ---------------- K6: final reductions + outputs -------------------------------
__global__ __launch_bounds__(256, 1)
void finkern(float* __restrict__ out, int N, int B) {
    __shared__ float red[8];
    int tid = threadIdx.x;
    float s = 0.f;
    for (int i = tid; i < N; i += 256) s += g_hinge[i];
    float hs = blk_reduce(s, red);
    float s2 = 0.f;
    for (int i = tid; i < B; i += 256) s2 += g_sq[i];
    float rsum = blk_reduce(s2, red);
    if (tid == 0) {
        float J = hs / (float)(N * NNEG);
        float rating = rsum / (float)B;
        float abae = g_U[0] + J;
        out[0] = rating + abae;   // obj (LR_RATING = LR_ABAE = 1)
        out[1] = rating;
        out[2] = abae;
    }
}

// ---------------- launch ------------------------------------------------------
extern "C" void kernel_launch(void* const* d_in, const int* in_sizes, int n_in,
                              void* d_out, int out_size) {
    const int*   hist  = (const int*)d_in[0];
    const float* rpos  = (const float*)d_in[1];
    const float* rneg  = (const float*)d_in[2];
    // d_in[3] (user), d_in[4] (item) unused by the reference
    const float* label = (const float*)d_in[5];
    const int*   uhi   = (const int*)d_in[6];
    const int*   usi   = (const int*)d_in[7];
    const int*   ihi   = (const int*)d_in[8];
    const int*   isi   = (const int*)d_in[9];
    const float* wemb  = (const float*)d_in[10];
    const float* Mw    = (const float*)d_in[11];
    const float* Ww    = (const float*)d_in[12];
    const float* Wb    = (const float*)d_in[13];
    const float* Tw    = (const float*)d_in[14];
    float* out = (float*)d_out;
    int F = in_sizes[6];

    const int SMEM_QK   = (DW * DW + 16 * DW) * 4;                        // 172800 B
    const int SMEM_MAIN = (25600 + 200 + 128 + 200 + 32 + 32 + 128) * 4;  // 105280 B
    cudaFuncSetAttribute(qk, cudaFuncAttributeMaxDynamicSharedMemorySize, SMEM_QK);
    cudaFuncSetAttribute(mainkern, cudaFuncAttributeMaxDynamicSharedMemorySize, SMEM_MAIN);

    qk<<<NREV / 16, 256, SMEM_QK>>>(rpos, Mw);
    mainkern<<<NREV, 256, SMEM_MAIN>>>(hist, wemb, rneg, Ww, Wb, Tw);
    ukern<<<1, 256>>>(Tw);
    segkern<<<dim3(BUSR, 2), 256>>>(uhi, usi, ihi, isi, F);
    predkern<<<(BUSR + 255) / 256, 256>>>(label, BUSR);
    finkern<<<1, 256>>>(out, NREV, BUSR);
}

// round 2
// speedup vs baseline: 1.6797x; 1.6797x over previous
#include <cuda_runtime.h>
#include <math.h>

#define NREV 4096
#define LTOK 128
#define DW   200
#define AASP 32
#define NNEG 5
#define BUSR 1024

// ---------------- scratch (device globals) -----------------------------------
__device__ __align__(16) float g_q[NREV * DW];
__device__ __align__(16) float g_rs[NREV * DW];
__device__ float g_hinge[NREV];
__device__ __align__(16) float g_uemb[BUSR * DW];
__device__ __align__(16) float g_iemb[BUSR * DW];
__device__ float g_U[1];

__device__ __forceinline__ float dot4(float4 a, float4 b) {
    return a.x * b.x + a.y * b.y + a.z * b.z + a.w * b.w;
}
__device__ __forceinline__ float warp_sum(float v) {
    #pragma unroll
    for (int o = 16; o; o >>= 1) v += __shfl_down_sync(0xffffffffu, v, o);
    return v;
}

// ---------------- K1: q = rev_pos @ M_w --------------------------------------
// 32 reviews per CTA -> 128 CTAs = 1 wave on 148 SMs. Warp handles 4 reviews,
// lane covers d = lane + 32k (k<7). M_w staged once in SMEM.
__global__ __launch_bounds__(256, 1)
void qk(const float* __restrict__ rp, const float* __restrict__ Mw) {
    extern __shared__ float sm[];
    float* Ms  = sm;            // 40000
    float* rps = sm + DW * DW;  // 32*200
    int tid = threadIdx.x, w = tid >> 5, lane = tid & 31;
    for (int i = tid; i < DW * DW; i += 256) Ms[i] = Mw[i];
    int n0 = blockIdx.x * 32;
    for (int i = tid; i < 32 * DW; i += 256) rps[i] = rp[n0 * DW + i];
    __syncthreads();

    float acc[4][7];
    #pragma unroll
    for (int j = 0; j < 4; j++)
        #pragma unroll
        for (int k = 0; k < 7; k++) acc[j][k] = 0.f;

    for (int d2 = 0; d2 < DW; d2++) {
        float m[7];
        #pragma unroll
        for (int k = 0; k < 7; k++) {
            int d = lane + 32 * k;
            m[k] = (d < DW) ? Ms[d2 * DW + d] : 0.f;
        }
        #pragma unroll
        for (int j = 0; j < 4; j++) {
            float r = rps[(w * 4 + j) * DW + d2];
            #pragma unroll
            for (int k = 0; k < 7; k++) acc[j][k] += r * m[k];
        }
    }
    #pragma unroll
    for (int j = 0; j < 4; j++)
        #pragma unroll
        for (int k = 0; k < 7; k++) {
            int d = lane + 32 * k;
            if (d < DW) g_q[(n0 + w * 4 + j) * DW + d] = acc[j][k];
        }
}

// ---------------- K2: fused per-review ABAE (+ U_loss block) -----------------
// SMEM floats: e 25600 | qs 200 | ax 128 | zs 200 | p 32 | part 208 | tot 16 | tok 128(int)
#define SM_E    0
#define SM_QS   25600
#define SM_AX   25800
#define SM_ZS   25928
#define SM_P    26128
#define SM_PART 26160
#define SM_TOT  26368
#define SM_TOK  26384
#define SM_MAIN_WORDS (26384 + 128)

__global__ __launch_bounds__(512, 2)
void mainkern(const int* __restrict__ hist, const float* __restrict__ wemb,
              const float* __restrict__ rneg, const float* __restrict__ Ww,
              const float* __restrict__ Wb, const float* __restrict__ Tw) {
    extern __shared__ float sm[];
    int n = blockIdx.x;
    int tid = threadIdx.x, w = tid >> 5, lane = tid & 31;

    // -------- extra block: U_loss --------
    if (n == NREV) {
        float* Ts  = sm;          // 6400
        float* nrm = sm + 6400;   // 32
        float* red = sm + 6432;   // 16
        for (int i = tid; i < DW * AASP; i += 512) Ts[i] = Tw[i];
        __syncthreads();
        if (tid < AASP) {
            float s = 0.f;
            for (int d = 0; d < DW; d++) { float v = Ts[d * AASP + tid]; s += v * v; }
            nrm[tid] = fmaxf(sqrtf(s), 1e-12f);
        }
        __syncthreads();
        float part = 0.f;
        for (int pr = tid; pr < AASP * AASP; pr += 512) {
            int a = pr >> 5, b = pr & 31;
            float s = 0.f;
            for (int d = 0; d < DW; d++) s += Ts[d * AASP + a] * Ts[d * AASP + b];
            float g = s / (nrm[a] * nrm[b]);
            float diff = g - ((a == b) ? 1.f : 0.f);
            part += diff * diff;
        }
        float v = warp_sum(part);
        if (lane == 0) red[w] = v;
        __syncthreads();
        if (tid == 0) {
            float t = 0.f;
            for (int k = 0; k < 16; k++) t += red[k];
            g_U[0] = t / (float)(AASP * AASP);
        }
        return;
    }

    float* e  = sm + SM_E;
    float* qs = sm + SM_QS;
    float* ax = sm + SM_AX;
    float* zs = sm + SM_ZS;
    float* p  = sm + SM_P;
    float* part = sm + SM_PART;
    float* tot  = sm + SM_TOT;
    int*   tok  = (int*)(sm + SM_TOK);

    if (tid < LTOK) tok[tid] = hist[n * LTOK + tid];
    if (tid < DW)   qs[tid]  = g_q[n * DW + tid];
    __syncthreads();

    // -------- gather e_w: 6400 float4, high MLP --------
    const float4* we4 = (const float4*)wemb;
    float4* e4 = (float4*)e;
    int ridx[13];
    #pragma unroll
    for (int k = 0; k < 13; k++) {
        int i = tid + k * 512;
        if (i < LTOK * 50) {
            int l = i / 50, c = i - l * 50;
            ridx[k] = tok[l] * 50 + c;
        } else ridx[k] = 0;
    }
    #pragma unroll
    for (int k = 0; k < 13; k++) {
        int i = tid + k * 512;
        if (i < LTOK * 50) e4[i] = __ldg(&we4[ridx[k]]);
    }
    __syncthreads();

    // -------- dx[l] = e_w[l].q  (warp w: tokens w*8..w*8+7) --------
    {
        const float4* qs4 = (const float4*)qs;
        float4 qv0 = qs4[lane];
        float4 qv1 = (lane < 18) ? qs4[32 + lane] : make_float4(0, 0, 0, 0);
        #pragma unroll
        for (int t = 0; t < 8; t++) {
            int l = w * 8 + t;
            const float4* er = (const float4*)(e + l * DW);
            float acc = dot4(er[lane], qv0);
            if (lane < 18) acc += dot4(er[32 + lane], qv1);
            acc = warp_sum(acc);
            if (lane == 0) ax[l] = acc;
        }
    }
    __syncthreads();

    // -------- softmax over 128 tokens (warp 0) --------
    if (w == 0) {
        float v0 = ax[lane], v1 = ax[lane + 32], v2 = ax[lane + 64], v3 = ax[lane + 96];
        float m = fmaxf(fmaxf(v0, v1), fmaxf(v2, v3));
        #pragma unroll
        for (int o = 16; o; o >>= 1) m = fmaxf(m, __shfl_xor_sync(0xffffffffu, m, o));
        v0 = expf(v0 - m); v1 = expf(v1 - m); v2 = expf(v2 - m); v3 = expf(v3 - m);
        float s = v0 + v1 + v2 + v3;
        #pragma unroll
        for (int o = 16; o; o >>= 1) s += __shfl_xor_sync(0xffffffffu, s, o);
        float inv = 1.f / s;
        ax[lane] = v0 * inv; ax[lane + 32] = v1 * inv;
        ax[lane + 64] = v2 * inv; ax[lane + 96] = v3 * inv;
    }
    __syncthreads();

    // -------- z_s (reshape trick): z[d] = sum_l e_flat[d*128+l]*ax[l] --------
    {
        const float4* ax4 = (const float4*)ax;
        float4 av = ax4[lane];
        for (int d = w; d < DW; d += 16) {
            const float4* ed = (const float4*)(e + d * LTOK);
            float acc = dot4(ed[lane], av);
            acc = warp_sum(acc);
            if (lane == 0) zs[d] = acc;
        }
    }
    __syncthreads();

    // -------- logits = z_s @ W_w^T + W_b  (warp w: aspects w, w+16) --------
    {
        const float4* zs4 = (const float4*)zs;
        float4 zv0 = zs4[lane];
        float4 zv1 = (lane < 18) ? zs4[32 + lane] : make_float4(0, 0, 0, 0);
        #pragma unroll
        for (int j = 0; j < 2; j++) {
            int a = w + 16 * j;
            const float4* wr = (const float4*)(Ww + a * DW);
            float acc = dot4(__ldg(&wr[lane]), zv0);
            if (lane < 18) acc += dot4(__ldg(&wr[32 + lane]), zv1);
            acc = warp_sum(acc);
            if (lane == 0) p[a] = acc + Wb[a];
        }
    }
    __syncthreads();

    // -------- softmax over A=32 (warp 0) --------
    if (w == 0) {
        float v = p[lane];
        float m = v;
        #pragma unroll
        for (int o = 16; o; o >>= 1) m = fmaxf(m, __shfl_xor_sync(0xffffffffu, m, o));
        float ex = expf(v - m);
        float s = ex;
        #pragma unroll
        for (int o = 16; o; o >>= 1) s += __shfl_xor_sync(0xffffffffu, s, o);
        p[lane] = ex / s;
    }
    __syncthreads();

    // -------- r_s = p @ T_w^T ; load negatives; 13 fused dot products --------
    float rsv = 0.f, zsv = 0.f, ng[NNEG];
    #pragma unroll
    for (int k = 0; k < NNEG; k++) ng[k] = 0.f;
    if (tid < DW) {
        const float4* T4 = (const float4*)(Tw + tid * AASP);
        float acc = 0.f;
        #pragma unroll
        for (int j = 0; j < 8; j++) {
            float4 t = __ldg(&T4[j]);
            acc += t.x * p[j * 4 + 0] + t.y * p[j * 4 + 1]
                 + t.z * p[j * 4 + 2] + t.w * p[j * 4 + 3];
        }
        g_rs[n * DW + tid] = acc;
        rsv = acc;
        zsv = zs[tid];
        #pragma unroll
        for (int k = 0; k < NNEG; k++)
            ng[k] = __ldg(&rneg[(n * NNEG + k) * DW + tid]);
    }

    float v[13];
    v[0] = zsv * zsv; v[1] = rsv * rsv; v[2] = zsv * rsv;
    #pragma unroll
    for (int k = 0; k < NNEG; k++) { v[3 + k] = ng[k] * ng[k]; v[8 + k] = ng[k] * rsv; }
    #pragma unroll
    for (int x = 0; x < 13; x++) v[x] = warp_sum(v[x]);
    if (lane == 0) {
        #pragma unroll
        for (int x = 0; x < 13; x++) part[w * 13 + x] = v[x];
    }
    __syncthreads();
    if (w == 0 && lane < 13) {
        float s = 0.f;
        #pragma unroll
        for (int k = 0; k < 16; k++) s += part[k * 13 + lane];
        tot[lane] = s;
    }
    __syncthreads();
    if (tid == 0) {
        float nz = fmaxf(sqrtf(tot[0]), 1e-12f);
        float nr = fmaxf(sqrtf(tot[1]), 1e-12f);
        float c1 = tot[2] / (nz * nr);
        float h = 0.f;
        #pragma unroll
        for (int k = 0; k < NNEG; k++) {
            float c2 = tot[8 + k] / (fmaxf(sqrtf(tot[3 + k]), 1e-12f) * nr);
            h += fmaxf(0.f, c2 - c1);
        }
        g_hinge[n] = h;
    }
}

// ---------------- K3: segment means (j unrolled x4 for MLP) -------------------
__global__ __launch_bounds__(256, 8)
void segkern(const int* __restrict__ uhi, const int* __restrict__ usi,
             const int* __restrict__ ihi, const int* __restrict__ isi, int F) {
    int b = blockIdx.x;
    const int* idx = blockIdx.y ? ihi : uhi;
    const int* seg = blockIdx.y ? isi : usi;
    float* out = blockIdx.y ? g_iemb : g_uemb;
    __shared__ int bnd[2];
    if (threadIdx.x == 0) {
        int lo = 0, hi = F;
        while (lo < hi) { int m = (lo + hi) >> 1; if (seg[m] < b) lo = m + 1; else hi = m; }
        bnd[0] = lo;
        int lo2 = lo, hi2 = F;
        while (lo2 < hi2) { int m = (lo2 + hi2) >> 1; if (seg[m] < b + 1) lo2 = m + 1; else hi2 = m; }
        bnd[1] = lo2;
    }
    __syncthreads();
    int lo = bnd[0], cnt = bnd[1] - bnd[0];
    float inv = 1.f / (float)cnt;
    int d = threadIdx.x;
    if (d < DW) {
        float s0 = 0.f, s1 = 0.f, s2 = 0.f, s3 = 0.f;
        int j = 0;
        for (; j + 4 <= cnt; j += 4) {
            int i0 = idx[lo + j], i1 = idx[lo + j + 1];
            int i2 = idx[lo + j + 2], i3 = idx[lo + j + 3];
            s0 += g_rs[i0 * DW + d];
            s1 += g_rs[i1 * DW + d];
            s2 += g_rs[i2 * DW + d];
            s3 += g_rs[i3 * DW + d];
        }
        for (; j < cnt; j++) s0 += g_rs[idx[lo + j] * DW + d];
        out[b * DW + d] = ((s0 + s1) + (s2 + s3)) * inv;
    }
}

// ---------------- K4: prediction + final reductions (one block) ---------------
__global__ __launch_bounds__(1024, 1)
void finkern(const float* __restrict__ label, float* __restrict__ out) {
    __shared__ float sc[32];
    int tid = threadIdx.x, w = tid >> 5, lane = tid & 31;

    // hinge sum
    float s = 0.f;
    for (int i = tid; i < NREV; i += 1024) s += g_hinge[i];
    s = warp_sum(s);
    if (lane == 0) sc[w] = s;
    __syncthreads();
    float hs = 0.f;
    if (tid == 0) for (int k = 0; k < 32; k++) hs += sc[k];
    __syncthreads();

    // prediction squared error: warp per b
    float sq = 0.f;
    for (int b = w; b < BUSR; b += 32) {
        const float4* u4 = (const float4*)(g_uemb + b * DW);
        const float4* i4 = (const float4*)(g_iemb + b * DW);
        float acc = dot4(u4[lane], i4[lane]);
        if (lane < 18) acc += dot4(u4[32 + lane], i4[32 + lane]);
        acc = warp_sum(acc);
        if (lane == 0) {
            float e = acc + 3.5f - label[b];
            sq += e * e;
        }
    }
    if (lane == 0) sc[w] = sq;
    __syncthreads();
    if (tid == 0) {
        float rsum = 0.f;
        for (int k = 0; k < 32; k++) rsum += sc[k];
        float rating = rsum / (float)BUSR;
        float J = hs / (float)(NREV * NNEG);
        float abae = g_U[0] + J;
        out[0] = rating + abae;
        out[1] = rating;
        out[2] = abae;
    }
}

// ---------------- launch ------------------------------------------------------
extern "C" void kernel_launch(void* const* d_in, const int* in_sizes, int n_in,
                              void* d_out, int out_size) {
    const int*   hist  = (const int*)d_in[0];
    const float* rpos  = (const float*)d_in[1];
    const float* rneg  = (const float*)d_in[2];
    const float* label = (const float*)d_in[5];
    const int*   uhi   = (const int*)d_in[6];
    const int*   usi   = (const int*)d_in[7];
    const int*   ihi   = (const int*)d_in[8];
    const int*   isi   = (const int*)d_in[9];
    const float* wemb  = (const float*)d_in[10];
    const float* Mw    = (const float*)d_in[11];
    const float* Ww    = (const float*)d_in[12];
    const float* Wb    = (const float*)d_in[13];
    const float* Tw    = (const float*)d_in[14];
    float* out = (float*)d_out;
    int F = in_sizes[6];

    const int SMEM_QK   = (DW * DW + 32 * DW) * 4;   // 185600 B
    const int SMEM_MAIN = SM_MAIN_WORDS * 4;         // 106048 B
    cudaFuncSetAttribute(qk, cudaFuncAttributeMaxDynamicSharedMemorySize, SMEM_QK);
    cudaFuncSetAttribute(mainkern, cudaFuncAttributeMaxDynamicSharedMemorySize, SMEM_MAIN);

    qk<<<NREV / 32, 256, SMEM_QK>>>(rpos, Mw);
    mainkern<<<NREV + 1, 512, SMEM_MAIN>>>(hist, wemb, rneg, Ww, Wb, Tw);
    segkern<<<dim3(BUSR, 2), 256>>>(uhi, usi, ihi, isi, F);
    finkern<<<1, 1024>>>(label, out);
}

// round 3
// speedup vs baseline: 2.0558x; 1.2239x over previous
#include <cuda_runtime.h>
#include <math.h>

#define NREV 4096
#define LTOK 128
#define DW   200
#define AASP 32
#define NNEG 5
#define BUSR 1024

// ---------------- scratch (device globals) -----------------------------------
__device__ __align__(16) float g_q[NREV * DW];
__device__ __align__(16) float g_rs[NREV * DW];
__device__ float g_hinge[NREV];
__device__ __align__(16) float g_uemb[BUSR * DW];
__device__ __align__(16) float g_iemb[BUSR * DW];
__device__ float g_sq[BUSR];
__device__ float g_U[1];

__device__ __forceinline__ float dot4(float4 a, float4 b) {
    return a.x * b.x + a.y * b.y + a.z * b.z + a.w * b.w;
}
__device__ __forceinline__ float warp_sum(float v) {
    #pragma unroll
    for (int o = 16; o; o >>= 1) v += __shfl_down_sync(0xffffffffu, v, o);
    return v;
}

// ---------------- K1: q = rev_pos @ M_w (vectorized) -------------------------
// 32 reviews/CTA -> 128 CTAs = 1 wave. Warp = 4 reviews; lane covers float4
// chunks c and c+32 of the 50-chunk output row. 12 LDS per 4 k-steps.
__global__ __launch_bounds__(256, 1)
void qk(const float* __restrict__ rp, const float* __restrict__ Mw) {
    extern __shared__ float sm[];
    float* Ms  = sm;            // 40000
    float* rps = sm + DW * DW;  // 6400
    int tid = threadIdx.x, w = tid >> 5, lane = tid & 31;
    for (int i = tid; i < DW * DW; i += 256) Ms[i] = Mw[i];
    int n0 = blockIdx.x * 32;
    for (int i = tid; i < 32 * DW; i += 256) rps[i] = rp[n0 * DW + i];
    __syncthreads();

    const float4* Ms4  = (const float4*)Ms;
    const float4* rps4 = (const float4*)rps;
    bool hi = (lane < 18);

    float4 acc[4][2];
    #pragma unroll
    for (int j = 0; j < 4; j++) {
        acc[j][0] = make_float4(0, 0, 0, 0);
        acc[j][1] = make_float4(0, 0, 0, 0);
    }

    for (int d2b = 0; d2b < 50; d2b++) {
        float4 r4[4];
        #pragma unroll
        for (int j = 0; j < 4; j++) r4[j] = rps4[(w * 4 + j) * 50 + d2b];
        #pragma unroll
        for (int s = 0; s < 4; s++) {
            int d2 = d2b * 4 + s;
            float4 m0 = Ms4[d2 * 50 + lane];
            float4 m1 = hi ? Ms4[d2 * 50 + 32 + lane] : make_float4(0, 0, 0, 0);
            #pragma unroll
            for (int j = 0; j < 4; j++) {
                float r = (s == 0) ? r4[j].x : (s == 1) ? r4[j].y : (s == 2) ? r4[j].z : r4[j].w;
                acc[j][0].x += r * m0.x; acc[j][0].y += r * m0.y;
                acc[j][0].z += r * m0.z; acc[j][0].w += r * m0.w;
                acc[j][1].x += r * m1.x; acc[j][1].y += r * m1.y;
                acc[j][1].z += r * m1.z; acc[j][1].w += r * m1.w;
            }
        }
    }
    float4* gq4 = (float4*)g_q;
    #pragma unroll
    for (int j = 0; j < 4; j++) {
        int row = (n0 + w * 4 + j) * 50;
        gq4[row + lane] = acc[j][0];
        if (hi) gq4[row + 32 + lane] = acc[j][1];
    }
}

// ---------------- K2: fused per-review ABAE (+ U_loss block) -----------------
#define SM_E    0
#define SM_QS   25600
#define SM_AX   25800
#define SM_ZS   25928
#define SM_P    26128
#define SM_PART 26160
#define SM_TOT  26368
#define SM_TOK  26384
#define SM_MAIN_WORDS (26384 + 128)

__global__ __launch_bounds__(512, 2)
void mainkern(const int* __restrict__ hist, const float* __restrict__ wemb,
              const float* __restrict__ rneg, const float* __restrict__ Ww,
              const float* __restrict__ Wb, const float* __restrict__ Tw) {
    extern __shared__ float sm[];
    int n = blockIdx.x;
    int tid = threadIdx.x, w = tid >> 5, lane = tid & 31;

    // -------- extra block: U_loss --------
    if (n == NREV) {
        float* Ts  = sm;
        float* nrm = sm + 6400;
        float* red = sm + 6432;
        for (int i = tid; i < DW * AASP; i += 512) Ts[i] = Tw[i];
        __syncthreads();
        if (tid < AASP) {
            float s = 0.f;
            for (int d = 0; d < DW; d++) { float v = Ts[d * AASP + tid]; s += v * v; }
            nrm[tid] = fmaxf(sqrtf(s), 1e-12f);
        }
        __syncthreads();
        float part = 0.f;
        for (int pr = tid; pr < AASP * AASP; pr += 512) {
            int a = pr >> 5, b = pr & 31;
            float s = 0.f;
            for (int d = 0; d < DW; d++) s += Ts[d * AASP + a] * Ts[d * AASP + b];
            float g = s / (nrm[a] * nrm[b]);
            float diff = g - ((a == b) ? 1.f : 0.f);
            part += diff * diff;
        }
        float v = warp_sum(part);
        if (lane == 0) red[w] = v;
        __syncthreads();
        if (tid == 0) {
            float t = 0.f;
            for (int k = 0; k < 16; k++) t += red[k];
            g_U[0] = t / (float)(AASP * AASP);
        }
        return;
    }

    float* e    = sm + SM_E;
    float* qs   = sm + SM_QS;
    float* ax   = sm + SM_AX;
    float* zs   = sm + SM_ZS;
    float* p    = sm + SM_P;
    float* part = sm + SM_PART;
    float* tot  = sm + SM_TOT;
    int*   tok  = (int*)(sm + SM_TOK);

    if (tid < LTOK) tok[tid] = hist[n * LTOK + tid];
    if (tid < DW)   qs[tid]  = g_q[n * DW + tid];
    __syncthreads();

    bool hi = (lane < 18);
    const float4* qs4 = (const float4*)qs;
    float4 qv0 = qs4[lane];
    float4 qv1 = hi ? qs4[32 + lane] : make_float4(0, 0, 0, 0);

    // -------- fused gather + dx: warp w owns tokens w*8..w*8+7 --------
    const float4* we4 = (const float4*)wemb;
    float4* e4 = (float4*)e;
    #pragma unroll
    for (int t0 = 0; t0 < 8; t0 += 4) {
        float4 v0[4], v1[4];
        #pragma unroll
        for (int t = 0; t < 4; t++) {
            int l = w * 8 + t0 + t;
            int rb = tok[l] * 50;
            v0[t] = __ldg(&we4[rb + lane]);
            v1[t] = hi ? __ldg(&we4[rb + 32 + lane]) : make_float4(0, 0, 0, 0);
        }
        float a[4];
        #pragma unroll
        for (int t = 0; t < 4; t++) {
            int l = w * 8 + t0 + t;
            e4[l * 50 + lane] = v0[t];
            if (hi) e4[l * 50 + 32 + lane] = v1[t];
            a[t] = dot4(v0[t], qv0) + dot4(v1[t], qv1);
        }
        #pragma unroll
        for (int t = 0; t < 4; t++) a[t] = warp_sum(a[t]);
        if (lane == 0) {
            #pragma unroll
            for (int t = 0; t < 4; t++) ax[w * 8 + t0 + t] = a[t];
        }
    }
    __syncthreads();

    // -------- softmax over 128 tokens (warp 0) --------
    if (w == 0) {
        float v0 = ax[lane], v1 = ax[lane + 32], v2 = ax[lane + 64], v3 = ax[lane + 96];
        float m = fmaxf(fmaxf(v0, v1), fmaxf(v2, v3));
        #pragma unroll
        for (int o = 16; o; o >>= 1) m = fmaxf(m, __shfl_xor_sync(0xffffffffu, m, o));
        v0 = expf(v0 - m); v1 = expf(v1 - m); v2 = expf(v2 - m); v3 = expf(v3 - m);
        float s = v0 + v1 + v2 + v3;
        #pragma unroll
        for (int o = 16; o; o >>= 1) s += __shfl_xor_sync(0xffffffffu, s, o);
        float inv = 1.f / s;
        ax[lane] = v0 * inv; ax[lane + 32] = v1 * inv;
        ax[lane + 64] = v2 * inv; ax[lane + 96] = v3 * inv;
    }
    __syncthreads();

    // -------- z_s (reshape trick), pairs for ILP --------
    {
        const float4* ax4 = (const float4*)ax;
        float4 av = ax4[lane];
        #pragma unroll
        for (int j = 0; j < 12; j += 2) {
            int d0 = w + 16 * j, d1 = w + 16 * (j + 1);
            const float4* ed0 = (const float4*)(e + d0 * LTOK);
            const float4* ed1 = (const float4*)(e + d1 * LTOK);
            float a0 = dot4(ed0[lane], av);
            float a1 = dot4(ed1[lane], av);
            a0 = warp_sum(a0);
            a1 = warp_sum(a1);
            if (lane == 0) { zs[d0] = a0; zs[d1] = a1; }
        }
        if (w < 8) {
            int d = w + 192;
            const float4* ed = (const float4*)(e + d * LTOK);
            float a = warp_sum(dot4(ed[lane], av));
            if (lane == 0) zs[d] = a;
        }
    }
    __syncthreads();

    // -------- logits = z_s @ W_w^T + W_b --------
    {
        const float4* zs4 = (const float4*)zs;
        float4 zv0 = zs4[lane];
        float4 zv1 = hi ? zs4[32 + lane] : make_float4(0, 0, 0, 0);
        #pragma unroll
        for (int j = 0; j < 2; j++) {
            int a = w + 16 * j;
            const float4* wr = (const float4*)(Ww + a * DW);
            float acc = dot4(__ldg(&wr[lane]), zv0);
            if (hi) acc += dot4(__ldg(&wr[32 + lane]), zv1);
            acc = warp_sum(acc);
            if (lane == 0) p[a] = acc + Wb[a];
        }
    }
    __syncthreads();

    // -------- softmax over A=32 (warp 0) --------
    if (w == 0) {
        float v = p[lane];
        float m = v;
        #pragma unroll
        for (int o = 16; o; o >>= 1) m = fmaxf(m, __shfl_xor_sync(0xffffffffu, m, o));
        float ex = expf(v - m);
        float s = ex;
        #pragma unroll
        for (int o = 16; o; o >>= 1) s += __shfl_xor_sync(0xffffffffu, s, o);
        p[lane] = ex / s;
    }
    __syncthreads();

    // -------- r_s = p @ T_w^T ; negatives; 13 fused dots --------
    float rsv = 0.f, zsv = 0.f, ng[NNEG];
    #pragma unroll
    for (int k = 0; k < NNEG; k++) ng[k] = 0.f;
    if (tid < DW) {
        const float4* T4 = (const float4*)(Tw + tid * AASP);
        float acc = 0.f;
        #pragma unroll
        for (int j = 0; j < 8; j++) {
            float4 t = __ldg(&T4[j]);
            acc += t.x * p[j * 4 + 0] + t.y * p[j * 4 + 1]
                 + t.z * p[j * 4 + 2] + t.w * p[j * 4 + 3];
        }
        g_rs[n * DW + tid] = acc;
        rsv = acc;
        zsv = zs[tid];
        #pragma unroll
        for (int k = 0; k < NNEG; k++)
            ng[k] = __ldg(&rneg[(n * NNEG + k) * DW + tid]);
    }

    float v[13];
    v[0] = zsv * zsv; v[1] = rsv * rsv; v[2] = zsv * rsv;
    #pragma unroll
    for (int k = 0; k < NNEG; k++) { v[3 + k] = ng[k] * ng[k]; v[8 + k] = ng[k] * rsv; }
    #pragma unroll
    for (int x = 0; x < 13; x++) v[x] = warp_sum(v[x]);
    if (lane == 0) {
        #pragma unroll
        for (int x = 0; x < 13; x++) part[w * 13 + x] = v[x];
    }
    __syncthreads();
    if (w == 0 && lane < 13) {
        float s = 0.f;
        #pragma unroll
        for (int k = 0; k < 16; k++) s += part[k * 13 + lane];
        tot[lane] = s;
    }
    __syncthreads();
    if (tid == 0) {
        float nz = fmaxf(sqrtf(tot[0]), 1e-12f);
        float nr = fmaxf(sqrtf(tot[1]), 1e-12f);
        float c1 = tot[2] / (nz * nr);
        float h = 0.f;
        #pragma unroll
        for (int k = 0; k < NNEG; k++) {
            float c2 = tot[8 + k] / (fmaxf(sqrtf(tot[3 + k]), 1e-12f) * nr);
            h += fmaxf(0.f, c2 - c1);
        }
        g_hinge[n] = h;
    }
}

// ---------------- K3: segment means ------------------------------------------
__global__ __launch_bounds__(256, 8)
void segkern(const int* __restrict__ uhi, const int* __restrict__ usi,
             const int* __restrict__ ihi, const int* __restrict__ isi, int F) {
    int b = blockIdx.x;
    const int* idx = blockIdx.y ? ihi : uhi;
    const int* seg = blockIdx.y ? isi : usi;
    float* out = blockIdx.y ? g_iemb : g_uemb;
    __shared__ int bnd[2];
    if (threadIdx.x == 0) {
        int lo = 0, hi = F;
        while (lo < hi) { int m = (lo + hi) >> 1; if (seg[m] < b) lo = m + 1; else hi = m; }
        bnd[0] = lo;
        int lo2 = lo, hi2 = F;
        while (lo2 < hi2) { int m = (lo2 + hi2) >> 1; if (seg[m] < b + 1) lo2 = m + 1; else hi2 = m; }
        bnd[1] = lo2;
    }
    __syncthreads();
    int lo = bnd[0], cnt = bnd[1] - bnd[0];
    float inv = 1.f / (float)cnt;
    int d = threadIdx.x;
    if (d < DW) {
        float s0 = 0.f, s1 = 0.f, s2 = 0.f, s3 = 0.f;
        int j = 0;
        for (; j + 4 <= cnt; j += 4) {
            int i0 = idx[lo + j], i1 = idx[lo + j + 1];
            int i2 = idx[lo + j + 2], i3 = idx[lo + j + 3];
            s0 += g_rs[i0 * DW + d];
            s1 += g_rs[i1 * DW + d];
            s2 += g_rs[i2 * DW + d];
            s3 += g_rs[i3 * DW + d];
        }
        for (; j < cnt; j++) s0 += g_rs[idx[lo + j] * DW + d];
        out[b * DW + d] = ((s0 + s1) + (s2 + s3)) * inv;
    }
}

// ---------------- K4: prediction squared errors (parallel) --------------------
__global__ __launch_bounds__(256, 4)
void predkern(const float* __restrict__ label) {
    int w = threadIdx.x >> 5, lane = threadIdx.x & 31;
    bool hi = (lane < 18);
    for (int b = blockIdx.x * 8 + w; b < BUSR; b += 256) {
        const float4* u4 = (const float4*)(g_uemb + b * DW);
        const float4* i4 = (const float4*)(g_iemb + b * DW);
        float acc = dot4(u4[lane], i4[lane]);
        if (hi) acc += dot4(u4[32 + lane], i4[32 + lane]);
        acc = warp_sum(acc);
        if (lane == 0) {
            float e = acc + 3.5f - label[b];
            g_sq[b] = e * e;
        }
    }
}

// ---------------- K5: final reductions ----------------------------------------
__global__ __launch_bounds__(1024, 1)
void finkern(float* __restrict__ out) {
    __shared__ float sc[32];
    int tid = threadIdx.x, w = tid >> 5, lane = tid & 31;

    float s = 0.f;
    for (int i = tid; i < NREV; i += 1024) s += g_hinge[i];
    s = warp_sum(s);
    if (lane == 0) sc[w] = s;
    __syncthreads();
    float hs = 0.f;
    if (tid == 0) for (int k = 0; k < 32; k++) hs += sc[k];
    __syncthreads();

    float s2 = 0.f;
    for (int i = tid; i < BUSR; i += 1024) s2 += g_sq[i];
    s2 = warp_sum(s2);
    if (lane == 0) sc[w] = s2;
    __syncthreads();
    if (tid == 0) {
        float rsum = 0.f;
        for (int k = 0; k < 32; k++) rsum += sc[k];
        float rating = rsum / (float)BUSR;
        float J = hs / (float)(NREV * NNEG);
        float abae = g_U[0] + J;
        out[0] = rating + abae;
        out[1] = rating;
        out[2] = abae;
    }
}

// ---------------- launch ------------------------------------------------------
extern "C" void kernel_launch(void* const* d_in, const int* in_sizes, int n_in,
                              void* d_out, int out_size) {
    const int*   hist  = (const int*)d_in[0];
    const float* rpos  = (const float*)d_in[1];
    const float* rneg  = (const float*)d_in[2];
    const float* label = (const float*)d_in[5];
    const int*   uhi   = (const int*)d_in[6];
    const int*   usi   = (const int*)d_in[7];
    const int*   ihi   = (const int*)d_in[8];
    const int*   isi   = (const int*)d_in[9];
    const float* wemb  = (const float*)d_in[10];
    const float* Mw    = (const float*)d_in[11];
    const float* Ww    = (const float*)d_in[12];
    const float* Wb    = (const float*)d_in[13];
    const float* Tw    = (const float*)d_in[14];
    float* out = (float*)d_out;
    int F = in_sizes[6];

    const int SMEM_QK   = (DW * DW + 32 * DW) * 4;   // 185600 B
    const int SMEM_MAIN = SM_MAIN_WORDS * 4;         // 106048 B
    cudaFuncSetAttribute(qk, cudaFuncAttributeMaxDynamicSharedMemorySize, SMEM_QK);
    cudaFuncSetAttribute(mainkern, cudaFuncAttributeMaxDynamicSharedMemorySize, SMEM_MAIN);

    qk<<<NREV / 32, 256, SMEM_QK>>>(rpos, Mw);
    mainkern<<<NREV + 1, 512, SMEM_MAIN>>>(hist, wemb, rneg, Ww, Wb, Tw);
    segkern<<<dim3(BUSR, 2), 256>>>(uhi, usi, ihi, isi, F);
    predkern<<<32, 256>>>(label);
    finkern<<<1, 1024>>>(out);
}

// round 4
// speedup vs baseline: 2.5104x; 1.2211x over previous
#include <cuda_runtime.h>
#include <math.h>

#define NREV 4096
#define LTOK 128
#define DW   200
#define AASP 32
#define NNEG 5
#define BUSR 1024

// ---------------- scratch (device globals) -----------------------------------
__device__ __align__(16) float g_q[NREV * DW];
__device__ __align__(16) float g_rs[NREV * DW];
__device__ float g_hinge[NREV];
__device__ __align__(16) float g_uemb[BUSR * DW];
__device__ __align__(16) float g_iemb[BUSR * DW];
__device__ float g_sq[BUSR];
__device__ float g_U[1];

__device__ __forceinline__ float dot4(float4 a, float4 b) {
    return a.x * b.x + a.y * b.y + a.z * b.z + a.w * b.w;
}
__device__ __forceinline__ float warp_sum(float v) {
    #pragma unroll
    for (int o = 16; o; o >>= 1) v += __shfl_down_sync(0xffffffffu, v, o);
    return v;
}

// ---------------- K1: q = rev_pos @ M_w (vectorized) -------------------------
__global__ __launch_bounds__(256, 1)
void qk(const float* __restrict__ rp, const float* __restrict__ Mw) {
    extern __shared__ float sm[];
    float* Ms  = sm;            // 40000
    float* rps = sm + DW * DW;  // 6400
    int tid = threadIdx.x, w = tid >> 5, lane = tid & 31;
    for (int i = tid; i < DW * DW; i += 256) Ms[i] = Mw[i];
    int n0 = blockIdx.x * 32;
    for (int i = tid; i < 32 * DW; i += 256) rps[i] = rp[n0 * DW + i];
    __syncthreads();

    const float4* Ms4  = (const float4*)Ms;
    const float4* rps4 = (const float4*)rps;
    bool hi = (lane < 18);

    float4 acc[4][2];
    #pragma unroll
    for (int j = 0; j < 4; j++) {
        acc[j][0] = make_float4(0, 0, 0, 0);
        acc[j][1] = make_float4(0, 0, 0, 0);
    }

    for (int d2b = 0; d2b < 50; d2b++) {
        float4 r4[4];
        #pragma unroll
        for (int j = 0; j < 4; j++) r4[j] = rps4[(w * 4 + j) * 50 + d2b];
        #pragma unroll
        for (int s = 0; s < 4; s++) {
            int d2 = d2b * 4 + s;
            float4 m0 = Ms4[d2 * 50 + lane];
            float4 m1 = hi ? Ms4[d2 * 50 + 32 + lane] : make_float4(0, 0, 0, 0);
            #pragma unroll
            for (int j = 0; j < 4; j++) {
                float r = (s == 0) ? r4[j].x : (s == 1) ? r4[j].y : (s == 2) ? r4[j].z : r4[j].w;
                acc[j][0].x += r * m0.x; acc[j][0].y += r * m0.y;
                acc[j][0].z += r * m0.z; acc[j][0].w += r * m0.w;
                acc[j][1].x += r * m1.x; acc[j][1].y += r * m1.y;
                acc[j][1].z += r * m1.z; acc[j][1].w += r * m1.w;
            }
        }
    }
    float4* gq4 = (float4*)g_q;
    #pragma unroll
    for (int j = 0; j < 4; j++) {
        int row = (n0 + w * 4 + j) * 50;
        gq4[row + lane] = acc[j][0];
        if (hi) gq4[row + 32 + lane] = acc[j][1];
    }
}

// ---------------- K2: fused per-review ABAE, no SMEM e-tile -------------------
// SMEM float layout (shared with U_loss block, total 6448 floats = 25.8KB):
//   qs 0..199 | ax 200..327 | zs 328..527 | p 528..559 | part 560..663
//   tot 664..679 | neg 680..1679 | tok(int) 1680..1807
__global__ __launch_bounds__(256, 4)
void mainkern(const int* __restrict__ hist, const float* __restrict__ wemb,
              const float* __restrict__ rneg, const float* __restrict__ Ww,
              const float* __restrict__ Wb, const float* __restrict__ Tw) {
    __shared__ float sm[6448];
    int n = blockIdx.x;
    int tid = threadIdx.x, w = tid >> 5, lane = tid & 31;

    // -------- extra block: U_loss --------
    if (n == NREV) {
        float* Ts  = sm;          // 6400
        float* nrm = sm + 6400;   // 32
        float* red = sm + 6432;   // 8
        for (int i = tid; i < DW * AASP; i += 256) Ts[i] = Tw[i];
        __syncthreads();
        if (tid < AASP) {
            float s = 0.f;
            for (int d = 0; d < DW; d++) { float v = Ts[d * AASP + tid]; s += v * v; }
            nrm[tid] = fmaxf(sqrtf(s), 1e-12f);
        }
        __syncthreads();
        float part = 0.f;
        for (int pr = tid; pr < AASP * AASP; pr += 256) {
            int a = pr >> 5, b = pr & 31;
            float s = 0.f;
            for (int d = 0; d < DW; d++) s += Ts[d * AASP + a] * Ts[d * AASP + b];
            float g = s / (nrm[a] * nrm[b]);
            float diff = g - ((a == b) ? 1.f : 0.f);
            part += diff * diff;
        }
        float v = warp_sum(part);
        if (lane == 0) red[w] = v;
        __syncthreads();
        if (tid == 0) {
            float t = 0.f;
            for (int k = 0; k < 8; k++) t += red[k];
            g_U[0] = t / (float)(AASP * AASP);
        }
        return;
    }

    float* qs   = sm;
    float* ax   = sm + 200;
    float* zs   = sm + 328;
    float* p    = sm + 528;
    float* part = sm + 560;
    float* tot  = sm + 664;
    float* neg  = sm + 680;
    int*   tok  = (int*)(sm + 1680);

    if (tid < LTOK) tok[tid] = hist[n * LTOK + tid];
    if (tid < DW)   qs[tid]  = g_q[n * DW + tid];
    {   // negatives -> SMEM (coalesced float4; 1000 floats)
        const float4* ng4 = (const float4*)(rneg + n * (NNEG * DW));
        float4* n4 = (float4*)neg;
        if (tid < 250) n4[tid] = __ldg(&ng4[tid]);
    }
    __syncthreads();

    bool hi = (lane < 18);
    const float4* qs4 = (const float4*)qs;
    float4 qv0 = qs4[lane];
    float4 qv1 = hi ? qs4[32 + lane] : make_float4(0, 0, 0, 0);
    const float4* we4 = (const float4*)wemb;

    // -------- gather + dx: warp w owns tokens w*16 .. w*16+15 --------
    #pragma unroll
    for (int t0 = 0; t0 < 16; t0 += 4) {
        float4 v0[4], v1[4];
        #pragma unroll
        for (int t = 0; t < 4; t++) {
            int rb = tok[w * 16 + t0 + t] * 50;
            v0[t] = __ldg(&we4[rb + lane]);
            v1[t] = hi ? __ldg(&we4[rb + 32 + lane]) : make_float4(0, 0, 0, 0);
        }
        float a[4];
        #pragma unroll
        for (int t = 0; t < 4; t++) a[t] = dot4(v0[t], qv0) + dot4(v1[t], qv1);
        #pragma unroll
        for (int t = 0; t < 4; t++) a[t] = warp_sum(a[t]);
        if (lane == 0) {
            #pragma unroll
            for (int t = 0; t < 4; t++) ax[w * 16 + t0 + t] = a[t];
        }
    }
    __syncthreads();

    // -------- softmax over 128 tokens (warp 0) --------
    if (w == 0) {
        float v0 = ax[lane], v1 = ax[lane + 32], v2 = ax[lane + 64], v3 = ax[lane + 96];
        float m = fmaxf(fmaxf(v0, v1), fmaxf(v2, v3));
        #pragma unroll
        for (int o = 16; o; o >>= 1) m = fmaxf(m, __shfl_xor_sync(0xffffffffu, m, o));
        v0 = expf(v0 - m); v1 = expf(v1 - m); v2 = expf(v2 - m); v3 = expf(v3 - m);
        float s = v0 + v1 + v2 + v3;
        #pragma unroll
        for (int o = 16; o; o >>= 1) s += __shfl_xor_sync(0xffffffffu, s, o);
        float inv = 1.f / s;
        ax[lane] = v0 * inv; ax[lane + 32] = v1 * inv;
        ax[lane + 64] = v2 * inv; ax[lane + 96] = v3 * inv;
    }
    __syncthreads();

    // -------- z_s re-gathered from L2 (contiguous flat slices) --------
    // z_s[d] = sum over pos in [d*128, d*128+128) of we[tok[pos/200], pos%200]*ax[pos&127]
    {
        const float4* ax4 = (const float4*)ax;
        float4 av = ax4[lane];          // ax[lane*4 .. +3], invariant across d
        #pragma unroll
        for (int j = 0; j < 24; j += 4) {
            int dd[4]; float4 f[4];
            #pragma unroll
            for (int k = 0; k < 4; k++) {
                dd[k] = w + 8 * (j + k);
                int pos = dd[k] * LTOK + lane * 4;
                int r = pos / 200;
                int c4 = (pos - r * 200) >> 2;
                f[k] = __ldg(&we4[tok[r] * 50 + c4]);
            }
            float a[4];
            #pragma unroll
            for (int k = 0; k < 4; k++) a[k] = dot4(f[k], av);
            #pragma unroll
            for (int k = 0; k < 4; k++) a[k] = warp_sum(a[k]);
            if (lane == 0) {
                #pragma unroll
                for (int k = 0; k < 4; k++) zs[dd[k]] = a[k];
            }
        }
        {   // leftover d = w + 192
            int d = w + 192;
            int pos = d * LTOK + lane * 4;
            int r = pos / 200;
            int c4 = (pos - r * 200) >> 2;
            float a = warp_sum(dot4(__ldg(&we4[tok[r] * 50 + c4]), av));
            if (lane == 0) zs[d] = a;
        }
    }
    __syncthreads();

    // -------- logits = z_s @ W_w^T + W_b (warp w: aspects w+8j) --------
    {
        const float4* zs4 = (const float4*)zs;
        float4 zv0 = zs4[lane];
        float4 zv1 = hi ? zs4[32 + lane] : make_float4(0, 0, 0, 0);
        #pragma unroll
        for (int j = 0; j < 4; j++) {
            int a = w + 8 * j;
            const float4* wr = (const float4*)(Ww + a * DW);
            float acc = dot4(__ldg(&wr[lane]), zv0);
            if (hi) acc += dot4(__ldg(&wr[32 + lane]), zv1);
            acc = warp_sum(acc);
            if (lane == 0) p[a] = acc + Wb[a];
        }
    }
    __syncthreads();

    // -------- softmax over A=32 (warp 0) --------
    if (w == 0) {
        float v = p[lane];
        float m = v;
        #pragma unroll
        for (int o = 16; o; o >>= 1) m = fmaxf(m, __shfl_xor_sync(0xffffffffu, m, o));
        float ex = expf(v - m);
        float s = ex;
        #pragma unroll
        for (int o = 16; o; o >>= 1) s += __shfl_xor_sync(0xffffffffu, s, o);
        p[lane] = ex / s;
    }
    __syncthreads();

    // -------- r_s = p @ T_w^T ; 13 fused dots --------
    float rsv = 0.f, zsv = 0.f, ng[NNEG];
    #pragma unroll
    for (int k = 0; k < NNEG; k++) ng[k] = 0.f;
    if (tid < DW) {
        const float4* T4 = (const float4*)(Tw + tid * AASP);
        float acc = 0.f;
        #pragma unroll
        for (int j = 0; j < 8; j++) {
            float4 t = __ldg(&T4[j]);
            acc += t.x * p[j * 4 + 0] + t.y * p[j * 4 + 1]
                 + t.z * p[j * 4 + 2] + t.w * p[j * 4 + 3];
        }
        g_rs[n * DW + tid] = acc;
        rsv = acc;
        zsv = zs[tid];
        #pragma unroll
        for (int k = 0; k < NNEG; k++) ng[k] = neg[k * DW + tid];
    }

    float v[13];
    v[0] = zsv * zsv; v[1] = rsv * rsv; v[2] = zsv * rsv;
    #pragma unroll
    for (int k = 0; k < NNEG; k++) { v[3 + k] = ng[k] * ng[k]; v[8 + k] = ng[k] * rsv; }
    #pragma unroll
    for (int x = 0; x < 13; x++) v[x] = warp_sum(v[x]);
    if (lane == 0) {
        #pragma unroll
        for (int x = 0; x < 13; x++) part[w * 13 + x] = v[x];
    }
    __syncthreads();
    if (w == 0 && lane < 13) {
        float s = 0.f;
        #pragma unroll
        for (int k = 0; k < 8; k++) s += part[k * 13 + lane];
        tot[lane] = s;
    }
    __syncthreads();
    if (tid == 0) {
        float nz = fmaxf(sqrtf(tot[0]), 1e-12f);
        float nr = fmaxf(sqrtf(tot[1]), 1e-12f);
        float c1 = tot[2] / (nz * nr);
        float h = 0.f;
        #pragma unroll
        for (int k = 0; k < NNEG; k++) {
            float c2 = tot[8 + k] / (fmaxf(sqrtf(tot[3 + k]), 1e-12f) * nr);
            h += fmaxf(0.f, c2 - c1);
        }
        g_hinge[n] = h;
    }
}

// ---------------- K3: segment means ------------------------------------------
__global__ __launch_bounds__(256, 8)
void segkern(const int* __restrict__ uhi, const int* __restrict__ usi,
             const int* __restrict__ ihi, const int* __restrict__ isi, int F) {
    int b = blockIdx.x;
    const int* idx = blockIdx.y ? ihi : uhi;
    const int* seg = blockIdx.y ? isi : usi;
    float* out = blockIdx.y ? g_iemb : g_uemb;
    __shared__ int bnd[2];
    if (threadIdx.x == 0) {
        int lo = 0, hi = F;
        while (lo < hi) { int m = (lo + hi) >> 1; if (seg[m] < b) lo = m + 1; else hi = m; }
        bnd[0] = lo;
        int lo2 = lo, hi2 = F;
        while (lo2 < hi2) { int m = (lo2 + hi2) >> 1; if (seg[m] < b + 1) lo2 = m + 1; else hi2 = m; }
        bnd[1] = lo2;
    }
    __syncthreads();
    int lo = bnd[0], cnt = bnd[1] - bnd[0];
    float inv = 1.f / (float)cnt;
    int d = threadIdx.x;
    if (d < DW) {
        float s0 = 0.f, s1 = 0.f, s2 = 0.f, s3 = 0.f;
        int j = 0;
        for (; j + 4 <= cnt; j += 4) {
            int i0 = idx[lo + j], i1 = idx[lo + j + 1];
            int i2 = idx[lo + j + 2], i3 = idx[lo + j + 3];
            s0 += g_rs[i0 * DW + d];
            s1 += g_rs[i1 * DW + d];
            s2 += g_rs[i2 * DW + d];
            s3 += g_rs[i3 * DW + d];
        }
        for (; j < cnt; j++) s0 += g_rs[idx[lo + j] * DW + d];
        out[b * DW + d] = ((s0 + s1) + (s2 + s3)) * inv;
    }
}

// ---------------- K4: prediction squared errors (warp per row) ----------------
__global__ __launch_bounds__(256, 4)
void predkern(const float* __restrict__ label) {
    int w = threadIdx.x >> 5, lane = threadIdx.x & 31;
    int b = blockIdx.x * 8 + w;
    if (b >= BUSR) return;
    bool hi = (lane < 18);
    const float4* u4 = (const float4*)(g_uemb + b * DW);
    const float4* i4 = (const float4*)(g_iemb + b * DW);
    float acc = dot4(u4[lane], i4[lane]);
    if (hi) acc += dot4(u4[32 + lane], i4[32 + lane]);
    acc = warp_sum(acc);
    if (lane == 0) {
        float e = acc + 3.5f - label[b];
        g_sq[b] = e * e;
    }
}

// ---------------- K5: final reductions ----------------------------------------
__global__ __launch_bounds__(1024, 1)
void finkern(float* __restrict__ out) {
    __shared__ float sc[32];
    int tid = threadIdx.x, w = tid >> 5, lane = tid & 31;

    float s = 0.f;
    for (int i = tid; i < NREV; i += 1024) s += g_hinge[i];
    s = warp_sum(s);
    if (lane == 0) sc[w] = s;
    __syncthreads();
    float hs = 0.f;
    if (tid == 0) for (int k = 0; k < 32; k++) hs += sc[k];
    __syncthreads();

    float s2 = 0.f;
    for (int i = tid; i < BUSR; i += 1024) s2 += g_sq[i];
    s2 = warp_sum(s2);
    if (lane == 0) sc[w] = s2;
    __syncthreads();
    if (tid == 0) {
        float rsum = 0.f;
        for (int k = 0; k < 32; k++) rsum += sc[k];
        float rating = rsum / (float)BUSR;
        float J = hs / (float)(NREV * NNEG);
        float abae = g_U[0] + J;
        out[0] = rating + abae;
        out[1] = rating;
        out[2] = abae;
    }
}

// ---------------- launch ------------------------------------------------------
extern "C" void kernel_launch(void* const* d_in, const int* in_sizes, int n_in,
                              void* d_out, int out_size) {
    const int*   hist  = (const int*)d_in[0];
    const float* rpos  = (const float*)d_in[1];
    const float* rneg  = (const float*)d_in[2];
    const float* label = (const float*)d_in[5];
    const int*   uhi   = (const int*)d_in[6];
    const int*   usi   = (const int*)d_in[7];
    const int*   ihi   = (const int*)d_in[8];
    const int*   isi   = (const int*)d_in[9];
    const float* wemb  = (const float*)d_in[10];
    const float* Mw    = (const float*)d_in[11];
    const float* Ww    = (const float*)d_in[12];
    const float* Wb    = (const float*)d_in[13];
    const float* Tw    = (const float*)d_in[14];
    float* out = (float*)d_out;
    int F = in_sizes[6];

    const int SMEM_QK = (DW * DW + 32 * DW) * 4;   // 185600 B
    cudaFuncSetAttribute(qk, cudaFuncAttributeMaxDynamicSharedMemorySize, SMEM_QK);

    qk<<<NREV / 32, 256, SMEM_QK>>>(rpos, Mw);
    mainkern<<<NREV + 1, 256>>>(hist, wemb, rneg, Ww, Wb, Tw);
    segkern<<<dim3(BUSR, 2), 256>>>(uhi, usi, ihi, isi, F);
    predkern<<<128, 256>>>(label);
    finkern<<<1, 1024>>>(out);
}